// round 1
// baseline (speedup 1.0000x reference)
#include <cuda_runtime.h>
#include <cuda_bf16.h>

#define NN 8192
#define DD 1024
#define SCALE 0.03125f   /* 1/sqrt(1024) */

// 256 MB scratch for S / P (in-place softmax), plus row sums.
__device__ float g_S[(size_t)NN * NN];
__device__ float g_rowsum[NN];

// ---------------------------------------------------------------------------
// GEMM1 (NT): S = Q * K^T * SCALE
// A = Q [8192 x 1024] row-major, B = K [8192 x 1024] row-major (used as B^T)
// Tile: BM=BN=128, BK=8, 256 threads, 8x8 per thread.
// ---------------------------------------------------------------------------
__global__ __launch_bounds__(256, 2) void qk_kernel(const float* __restrict__ Q,
                                                    const float* __restrict__ Km) {
    __shared__ float As[8][128];
    __shared__ float Bs[8][128];

    const int bm = blockIdx.y * 128;
    const int bn = blockIdx.x * 128;
    const int tid = threadIdx.x;
    const int tx = tid & 15;     // 0..15 -> N microtile
    const int ty = tid >> 4;     // 0..15 -> M microtile

    // Loader mapping: one float4 per thread per tile for A and B.
    const int lr = tid >> 1;          // 0..127 row in tile
    const int lc = (tid & 1) * 4;     // 0 or 4 col in BK

    const float* Ap = Q  + (size_t)(bm + lr) * DD + lc;
    const float* Bp = Km + (size_t)(bn + lr) * DD + lc;

    float acc[8][8];
#pragma unroll
    for (int i = 0; i < 8; i++)
#pragma unroll
        for (int j = 0; j < 8; j++) acc[i][j] = 0.0f;

    for (int k0 = 0; k0 < DD; k0 += 8) {
        float4 a = *(const float4*)(Ap + k0);
        float4 b = *(const float4*)(Bp + k0);
        As[lc + 0][lr] = a.x; As[lc + 1][lr] = a.y;
        As[lc + 2][lr] = a.z; As[lc + 3][lr] = a.w;
        Bs[lc + 0][lr] = b.x; Bs[lc + 1][lr] = b.y;
        Bs[lc + 2][lr] = b.z; Bs[lc + 3][lr] = b.w;
        __syncthreads();

#pragma unroll
        for (int kk = 0; kk < 8; kk++) {
            float ra[8], rb[8];
            *(float4*)&ra[0] = *(const float4*)&As[kk][ty * 8];
            *(float4*)&ra[4] = *(const float4*)&As[kk][ty * 8 + 4];
            *(float4*)&rb[0] = *(const float4*)&Bs[kk][tx * 8];
            *(float4*)&rb[4] = *(const float4*)&Bs[kk][tx * 8 + 4];
#pragma unroll
            for (int i = 0; i < 8; i++)
#pragma unroll
                for (int j = 0; j < 8; j++) acc[i][j] += ra[i] * rb[j];
        }
        __syncthreads();
    }

    float* Cp = g_S + (size_t)(bm + ty * 8) * NN + bn + tx * 8;
#pragma unroll
    for (int i = 0; i < 8; i++) {
        float4 o0 = make_float4(acc[i][0] * SCALE, acc[i][1] * SCALE,
                                acc[i][2] * SCALE, acc[i][3] * SCALE);
        float4 o1 = make_float4(acc[i][4] * SCALE, acc[i][5] * SCALE,
                                acc[i][6] * SCALE, acc[i][7] * SCALE);
        *(float4*)(Cp + (size_t)i * NN)     = o0;
        *(float4*)(Cp + (size_t)i * NN + 4) = o1;
    }
}

// ---------------------------------------------------------------------------
// Softmax (in place, unnormalized): S[row,:] = exp(S - rowmax); rowsum saved.
// Normalization is folded into the PV epilogue.
// One 256-thread block per row.
// ---------------------------------------------------------------------------
__global__ __launch_bounds__(256) void softmax_kernel() {
    const int row = blockIdx.x;
    const int tid = threadIdx.x;
    float4* p = (float4*)(g_S + (size_t)row * NN);
    __shared__ float red[256];

    // pass 1: max
    float m = -1e30f;
#pragma unroll
    for (int i = 0; i < 8; i++) {
        float4 v = p[tid + i * 256];
        m = fmaxf(m, fmaxf(fmaxf(v.x, v.y), fmaxf(v.z, v.w)));
    }
    red[tid] = m;
    __syncthreads();
#pragma unroll
    for (int s = 128; s > 0; s >>= 1) {
        if (tid < s) red[tid] = fmaxf(red[tid], red[tid + s]);
        __syncthreads();
    }
    m = red[0];
    __syncthreads();

    // pass 2: exp + sum
    float sum = 0.0f;
#pragma unroll
    for (int i = 0; i < 8; i++) {
        float4 v = p[tid + i * 256];
        v.x = __expf(v.x - m); v.y = __expf(v.y - m);
        v.z = __expf(v.z - m); v.w = __expf(v.w - m);
        sum += (v.x + v.y) + (v.z + v.w);
        p[tid + i * 256] = v;
    }
    red[tid] = sum;
    __syncthreads();
#pragma unroll
    for (int s = 128; s > 0; s >>= 1) {
        if (tid < s) red[tid] = red[tid] + red[tid + s];
        __syncthreads();
    }
    if (tid == 0) g_rowsum[row] = red[0];
}

// ---------------------------------------------------------------------------
// GEMM2 (NN): O = (P @ V) / rowsum
// A = P [8192 x 8192], B = V [8192 x 1024], C = O [8192 x 1024]
// ---------------------------------------------------------------------------
__global__ __launch_bounds__(256, 2) void pv_kernel(const float* __restrict__ V,
                                                    float* __restrict__ O) {
    __shared__ float As[8][128];
    __shared__ float Bs[8][128];

    const int bm = blockIdx.y * 128;
    const int bn = blockIdx.x * 128;
    const int tid = threadIdx.x;
    const int tx = tid & 15;
    const int ty = tid >> 4;

    // A loader: float4 along K, scatter-transpose into As
    const int lr = tid >> 1;
    const int lc = (tid & 1) * 4;
    const float* Ap = g_S + (size_t)(bm + lr) * NN + lc;

    // B loader: float4 along N (coalesced), direct store
    const int brow = tid >> 5;          // 0..7  (K within tile)
    const int bcol = (tid & 31) * 4;    // 0..124
    const float* Bp = V + (size_t)brow * DD + bn + bcol;

    float acc[8][8];
#pragma unroll
    for (int i = 0; i < 8; i++)
#pragma unroll
        for (int j = 0; j < 8; j++) acc[i][j] = 0.0f;

    for (int k0 = 0; k0 < NN; k0 += 8) {
        float4 a = *(const float4*)(Ap + k0);
        float4 b = *(const float4*)(Bp + (size_t)k0 * DD);
        As[lc + 0][lr] = a.x; As[lc + 1][lr] = a.y;
        As[lc + 2][lr] = a.z; As[lc + 3][lr] = a.w;
        *(float4*)&Bs[brow][bcol] = b;
        __syncthreads();

#pragma unroll
        for (int kk = 0; kk < 8; kk++) {
            float ra[8], rb[8];
            *(float4*)&ra[0] = *(const float4*)&As[kk][ty * 8];
            *(float4*)&ra[4] = *(const float4*)&As[kk][ty * 8 + 4];
            *(float4*)&rb[0] = *(const float4*)&Bs[kk][tx * 8];
            *(float4*)&rb[4] = *(const float4*)&Bs[kk][tx * 8 + 4];
#pragma unroll
            for (int i = 0; i < 8; i++)
#pragma unroll
                for (int j = 0; j < 8; j++) acc[i][j] += ra[i] * rb[j];
        }
        __syncthreads();
    }

    float* Cp = O + (size_t)(bm + ty * 8) * DD + bn + tx * 8;
#pragma unroll
    for (int i = 0; i < 8; i++) {
        const float inv = 1.0f / g_rowsum[bm + ty * 8 + i];
        float4 o0 = make_float4(acc[i][0] * inv, acc[i][1] * inv,
                                acc[i][2] * inv, acc[i][3] * inv);
        float4 o1 = make_float4(acc[i][4] * inv, acc[i][5] * inv,
                                acc[i][6] * inv, acc[i][7] * inv);
        *(float4*)(Cp + (size_t)i * DD)     = o0;
        *(float4*)(Cp + (size_t)i * DD + 4) = o1;
    }
}

// ---------------------------------------------------------------------------
extern "C" void kernel_launch(void* const* d_in, const int* in_sizes, int n_in,
                              void* d_out, int out_size) {
    const float* q = (const float*)d_in[0];
    const float* k = (const float*)d_in[1];
    const float* v = (const float*)d_in[2];
    float* out = (float*)d_out;

    qk_kernel<<<dim3(NN / 128, NN / 128), 256>>>(q, k);
    softmax_kernel<<<NN, 256>>>();
    pv_kernel<<<dim3(DD / 128, NN / 128), 256>>>(v, out);
}

// round 3
// speedup vs baseline: 3.8737x; 3.8737x over previous
#include <cuda_runtime.h>
#include <cstdint>

#define NN 8192
#define DD 1024

// Scratch buffers.
__device__ __align__(256) float    g_S [(size_t)NN * NN];   // raw QK^T scores (linear)
__device__ __align__(256) uint32_t g_Sp[(size_t)NN * NN];   // softmaxed P, A-permuted, tf32
__device__ __align__(256) uint32_t g_Ap[(size_t)NN * DD];   // Q*scale, A-permuted, tf32
__device__ __align__(256) uint32_t g_Bk[(size_t)NN * DD];   // K, B-permuted, tf32
__device__ __align__(256) uint32_t g_Bv[(size_t)DD * NN];   // V^T, B-permuted, tf32
__device__ float g_rowinv[NN];

// ---------------------------------------------------------------------------
// Helpers
// ---------------------------------------------------------------------------
__device__ __forceinline__ uint32_t smem_u32(const void* p) {
    uint32_t a;
    asm("{ .reg .u64 t; cvta.to.shared.u64 t, %1; cvt.u32.u64 %0, t; }" : "=r"(a) : "l"(p));
    return a;
}

__device__ __forceinline__ uint32_t f2tf32(float x) {
    uint32_t r;
    asm("cvt.rna.tf32.f32 %0, %1;" : "=r"(r) : "f"(x));
    return r;
}

__device__ __forceinline__ void cp_async16(uint32_t saddr, const void* gaddr) {
    asm volatile("cp.async.cg.shared.global [%0], [%1], 16;" :: "r"(saddr), "l"(gaddr) : "memory");
}

__device__ __forceinline__ void mma_tf32(float* c, const uint32_t* a, const uint32_t* b) {
    asm volatile(
        "mma.sync.aligned.m16n8k8.row.col.f32.tf32.tf32.f32 "
        "{%0,%1,%2,%3}, {%4,%5,%6,%7}, {%8,%9}, {%0,%1,%2,%3};"
        : "+f"(c[0]), "+f"(c[1]), "+f"(c[2]), "+f"(c[3])
        : "r"(a[0]), "r"(a[1]), "r"(a[2]), "r"(a[3]), "r"(b[0]), "r"(b[1]));
}

// A-side permuted layout: [M/16][K/8][32 threads][4 regs] of u32
// value (m,k): t = (m&7)*4 + (k&3), reg = ((m>>3)&1) + 2*((k>>2)&1)
__device__ __forceinline__ size_t offA(int m, int k, int kt8) {
    return ((size_t)(m >> 4) * kt8 + (k >> 3)) * 128
         + ((m & 7) * 4 + (k & 3)) * 4 + ((m >> 3) & 1) + ((k >> 2) & 1) * 2;
}
// B-side permuted layout: [N/8][K/8][32 threads][2 regs]
// value (n,k): t = (n&7)*4 + (k&3), reg = (k>>2)&1
__device__ __forceinline__ size_t offB(int n, int k, int kt8) {
    return ((size_t)(n >> 3) * kt8 + (k >> 3)) * 64
         + ((n & 7) * 4 + (k & 3)) * 2 + ((k >> 2) & 1);
}

// ---------------------------------------------------------------------------
// Prep kernels: tf32-round once, permute into mma-native layouts.
// ---------------------------------------------------------------------------
__global__ __launch_bounds__(256) void prep_q(const float* __restrict__ Q) {
    size_t idx = (size_t)blockIdx.x * 256 + threadIdx.x;
    int m = (int)(idx >> 10), k = (int)(idx & 1023);
    g_Ap[offA(m, k, 128)] = f2tf32(Q[idx] * 0.03125f);
}
__global__ __launch_bounds__(256) void prep_k(const float* __restrict__ K) {
    size_t idx = (size_t)blockIdx.x * 256 + threadIdx.x;
    int n = (int)(idx >> 10), k = (int)(idx & 1023);
    g_Bk[offB(n, k, 128)] = f2tf32(K[idx]);
}
__global__ __launch_bounds__(256) void prep_v(const float* __restrict__ V) {
    size_t idx = (size_t)blockIdx.x * 256 + threadIdx.x;
    int kseq = (int)(idx >> 10), n = (int)(idx & 1023);   // B: N-dim = headdim, K-dim = seq
    g_Bv[offB(n, kseq, 1024)] = f2tf32(V[idx]);
}

// ---------------------------------------------------------------------------
// Unified NT tf32 GEMM via mma.sync: D[m,n] = sum_k A[m,k]*B[n,k]
// CTA 128x128, BK=16, 8 warps (2M x 4N), warp tile 64x32, double buffer.
// mode 0: C[linear] = acc        mode 1: C = acc * rowinv[m]
// ---------------------------------------------------------------------------
struct GemmParams {
    const uint32_t* Ap;
    const uint32_t* Bp;
    float* C;
    const float* rowinv;
    int ldc;
    int kt8;     // K / 8
    int mode;
};

__global__ __launch_bounds__(256, 2) void gemm_mma(const GemmParams p) {
    __shared__ uint32_t smem[2][4096];   // per buf: A 2048 u32 (16 subtiles*128) + B 2048 (32*64)

    const int tid = threadIdx.x;
    const int wid = tid >> 5, lane = tid & 31;
    const int wm = wid & 1, wn = wid >> 1;
    const int bmt = blockIdx.y * 8;      // A subtile row base (m/16)
    const int bnt = blockIdx.x * 16;     // B subtile row base (n/8)
    const int KT = p.kt8 >> 1;           // BK=16 tiles

    // loader invariants (2 A chunks + 2 B chunks per thread per tile)
    const int a_st0 = tid >> 5,          a_t0 = lane;
    const int a_st1 = (tid + 256) >> 5,  a_t1 = lane;
    const int b_st0 = tid >> 4,          b_w0 = tid & 15;
    const int b_st1 = (tid + 256) >> 4,  b_w1 = tid & 15;

    const uint32_t sb0 = smem_u32(&smem[0][0]);
    const uint32_t sb1 = smem_u32(&smem[1][0]);

    auto load_tile = [&](int kt, int buf) {
        const uint32_t sb = buf ? sb1 : sb0;
        const uint32_t* Ag;
        Ag = p.Ap + ((size_t)(bmt + (a_st0 >> 1)) * p.kt8 + 2 * kt + (a_st0 & 1)) * 128 + a_t0 * 4;
        cp_async16(sb + (a_st0 * 128 + a_t0 * 4) * 4, Ag);
        Ag = p.Ap + ((size_t)(bmt + (a_st1 >> 1)) * p.kt8 + 2 * kt + (a_st1 & 1)) * 128 + a_t1 * 4;
        cp_async16(sb + (a_st1 * 128 + a_t1 * 4) * 4, Ag);
        const uint32_t* Bg;
        Bg = p.Bp + ((size_t)(bnt + (b_st0 >> 1)) * p.kt8 + 2 * kt + (b_st0 & 1)) * 64 + b_w0 * 4;
        cp_async16(sb + (2048 + b_st0 * 64 + b_w0 * 4) * 4, Bg);
        Bg = p.Bp + ((size_t)(bnt + (b_st1 >> 1)) * p.kt8 + 2 * kt + (b_st1 & 1)) * 64 + b_w1 * 4;
        cp_async16(sb + (2048 + b_st1 * 64 + b_w1 * 4) * 4, Bg);
        asm volatile("cp.async.commit_group;" ::: "memory");
    };

    float acc[4][4][4];
#pragma unroll
    for (int i = 0; i < 4; i++)
#pragma unroll
        for (int j = 0; j < 4; j++)
#pragma unroll
            for (int r = 0; r < 4; r++) acc[i][j][r] = 0.0f;

    load_tile(0, 0);

    for (int kt = 0; kt < KT; kt++) {
        if (kt + 1 < KT) {
            load_tile(kt + 1, (kt + 1) & 1);
            asm volatile("cp.async.wait_group 1;" ::: "memory");
        } else {
            asm volatile("cp.async.wait_group 0;" ::: "memory");
        }
        __syncthreads();

        const uint32_t* buf = smem[kt & 1];
#pragma unroll
        for (int kk = 0; kk < 2; kk++) {
            uint32_t a[4][4], b[4][2];
#pragma unroll
            for (int mt = 0; mt < 4; mt++) {
                const int st = (wm * 4 + mt) * 2 + kk;
                const uint4 v = *(const uint4*)(buf + st * 128 + lane * 4);
                a[mt][0] = v.x; a[mt][1] = v.y; a[mt][2] = v.z; a[mt][3] = v.w;
            }
#pragma unroll
            for (int nt = 0; nt < 4; nt++) {
                const int st = (wn * 4 + nt) * 2 + kk;
                const uint2 v = *(const uint2*)(buf + 2048 + st * 64 + lane * 2);
                b[nt][0] = v.x; b[nt][1] = v.y;
            }
#pragma unroll
            for (int mt = 0; mt < 4; mt++)
#pragma unroll
                for (int nt = 0; nt < 4; nt++)
                    mma_tf32(acc[mt][nt], a[mt], b[nt]);
        }
        __syncthreads();
    }

    // epilogue
    const int bm = blockIdx.y * 128, bn = blockIdx.x * 128;
#pragma unroll
    for (int mt = 0; mt < 4; mt++) {
        const int row = bm + wm * 64 + mt * 16 + (lane >> 2);
        const float f0 = p.mode ? p.rowinv[row]     : 1.0f;
        const float f1 = p.mode ? p.rowinv[row + 8] : 1.0f;
#pragma unroll
        for (int nt = 0; nt < 4; nt++) {
            const int col = bn + wn * 32 + nt * 8 + (lane & 3) * 2;
            float2 o0 = make_float2(acc[mt][nt][0] * f0, acc[mt][nt][1] * f0);
            float2 o1 = make_float2(acc[mt][nt][2] * f1, acc[mt][nt][3] * f1);
            *(float2*)(p.C + (size_t)row * p.ldc + col)       = o0;
            *(float2*)(p.C + (size_t)(row + 8) * p.ldc + col) = o1;
        }
    }
}

// ---------------------------------------------------------------------------
// Softmax: reads raw scores from g_S (linear), writes rna(exp(x-max)) into the
// A-permuted tf32 buffer g_Sp for GEMM2, and 1/rowsum into g_rowinv.
// ---------------------------------------------------------------------------
__global__ __launch_bounds__(256) void softmax_kernel() {
    const int row = blockIdx.x;
    const int tid = threadIdx.x;
    const float4* p = (const float4*)(g_S + (size_t)row * NN);
    __shared__ float red[256];

    float m = -1e30f;
#pragma unroll
    for (int i = 0; i < 8; i++) {
        float4 v = p[tid + i * 256];
        m = fmaxf(m, fmaxf(fmaxf(v.x, v.y), fmaxf(v.z, v.w)));
    }
    red[tid] = m;
    __syncthreads();
#pragma unroll
    for (int s = 128; s > 0; s >>= 1) {
        if (tid < s) red[tid] = fmaxf(red[tid], red[tid + s]);
        __syncthreads();
    }
    m = red[0];
    __syncthreads();

    const size_t mtbase = (size_t)(row >> 4) * 1024;
    const int tb = (row & 7) * 4;
    const int regb = (row >> 3) & 1;

    float sum = 0.0f;
#pragma unroll
    for (int i = 0; i < 8; i++) {
        const int k0 = (tid + i * 256) * 4;     // 4-aligned, so (k&3) = 0..3, (k>>2) fixed
        float4 v = p[tid + i * 256];
        float e0 = __expf(v.x - m), e1 = __expf(v.y - m);
        float e2 = __expf(v.z - m), e3 = __expf(v.w - m);
        sum += (e0 + e1) + (e2 + e3);
        const size_t sbase = (mtbase + (k0 >> 3)) * 128 + regb + ((k0 >> 2) & 1) * 2;
        g_Sp[sbase + (tb + 0) * 4] = f2tf32(e0);
        g_Sp[sbase + (tb + 1) * 4] = f2tf32(e1);
        g_Sp[sbase + (tb + 2) * 4] = f2tf32(e2);
        g_Sp[sbase + (tb + 3) * 4] = f2tf32(e3);
    }
    red[tid] = sum;
    __syncthreads();
#pragma unroll
    for (int s = 128; s > 0; s >>= 1) {
        if (tid < s) red[tid] = red[tid] + red[tid + s];
        __syncthreads();
    }
    if (tid == 0) g_rowinv[row] = 1.0f / red[0];
}

// ---------------------------------------------------------------------------
// Host
// ---------------------------------------------------------------------------
extern "C" void kernel_launch(void* const* d_in, const int* in_sizes, int n_in,
                              void* d_out, int out_size) {
    const float* q = (const float*)d_in[0];
    const float* k = (const float*)d_in[1];
    const float* v = (const float*)d_in[2];
    float* out = (float*)d_out;

    void *pS = nullptr, *pSp = nullptr, *pAp = nullptr, *pBk = nullptr,
         *pBv = nullptr, *pRi = nullptr;
    cudaGetSymbolAddress(&pS,  g_S);
    cudaGetSymbolAddress(&pSp, g_Sp);
    cudaGetSymbolAddress(&pAp, g_Ap);
    cudaGetSymbolAddress(&pBk, g_Bk);
    cudaGetSymbolAddress(&pBv, g_Bv);
    cudaGetSymbolAddress(&pRi, g_rowinv);

    const int prep_blocks = (int)(((size_t)NN * DD) / 256);
    prep_q<<<prep_blocks, 256>>>(q);
    prep_k<<<prep_blocks, 256>>>(k);
    prep_v<<<prep_blocks, 256>>>(v);

    GemmParams g1;
    g1.Ap = (const uint32_t*)pAp; g1.Bp = (const uint32_t*)pBk;
    g1.C = (float*)pS; g1.rowinv = nullptr;
    g1.ldc = NN; g1.kt8 = DD / 8; g1.mode = 0;
    gemm_mma<<<dim3(NN / 128, NN / 128), 256>>>(g1);

    softmax_kernel<<<NN, 256>>>();

    GemmParams g2;
    g2.Ap = (const uint32_t*)pSp; g2.Bp = (const uint32_t*)pBv;
    g2.C = out; g2.rowinv = (const float*)pRi;
    g2.ldc = DD; g2.kt8 = NN / 8; g2.mode = 1;
    gemm_mma<<<dim3(DD / 128, NN / 128), 256>>>(g2);
}

// round 5
// speedup vs baseline: 7.4848x; 1.9322x over previous
#include <cuda_runtime.h>
#include <cuda_fp16.h>
#include <cstdint>

#define NN 8192
#define DD 1024

// Scratch buffers.
__device__ __align__(256) float    g_S [(size_t)NN * NN];        // raw scores fp32 (256 MB)
__device__ __align__(256) uint32_t g_Sp[(size_t)NN * NN / 2];    // P, A-permuted fp16 (128 MB)
__device__ __align__(256) uint32_t g_Ap[(size_t)NN * DD / 2];    // Q*scale, A-permuted fp16
__device__ __align__(256) uint32_t g_Bk[(size_t)NN * DD / 2];    // K, B-permuted fp16
__device__ __align__(256) uint32_t g_Bv[(size_t)DD * NN / 2];    // V^T, B-permuted fp16
__device__ float g_rowinv[NN];

// ---------------------------------------------------------------------------
// Helpers
// ---------------------------------------------------------------------------
__device__ __forceinline__ uint32_t smem_u32(const void* p) {
    uint32_t a;
    asm("{ .reg .u64 t; cvta.to.shared.u64 t, %1; cvt.u32.u64 %0, t; }" : "=r"(a) : "l"(p));
    return a;
}

__device__ __forceinline__ void cp_async16(uint32_t saddr, const void* gaddr) {
    asm volatile("cp.async.cg.shared.global [%0], [%1], 16;" :: "r"(saddr), "l"(gaddr) : "memory");
}

__device__ __forceinline__ void mma_f16(float* c, const uint32_t* a, const uint32_t* b) {
    asm volatile(
        "mma.sync.aligned.m16n8k16.row.col.f32.f16.f16.f32 "
        "{%0,%1,%2,%3}, {%4,%5,%6,%7}, {%8,%9}, {%0,%1,%2,%3};"
        : "+f"(c[0]), "+f"(c[1]), "+f"(c[2]), "+f"(c[3])
        : "r"(a[0]), "r"(a[1]), "r"(a[2]), "r"(a[3]), "r"(b[0]), "r"(b[1]));
}

__device__ __forceinline__ uint32_t pack_h2(float lo, float hi) {
    __half2 h = __floats2half2_rn(lo, hi);
    return *(uint32_t*)&h;
}

// Fast exp(x) for x <= 0 via 2^t poly + exponent bit-trick. FMA/ALU pipe only.
__device__ __forceinline__ float fexp(float x) {
    x = fmaxf(x, -80.0f);
    const float L2E = 1.4426950408889634f;
    float z = fmaf(x, L2E, 12582912.0f);        // round-to-nearest via magic number
    float r = z - 12582912.0f;
    float f = fmaf(x, L2E, -r);                 // frac in [-0.5, 0.5]
    float p =              1.3333558e-3f;
    p = fmaf(p, f,         9.6181291e-3f);
    p = fmaf(p, f,         5.5504109e-2f);
    p = fmaf(p, f,         2.4022651e-1f);
    p = fmaf(p, f,         6.9314718e-1f);
    p = fmaf(p, f,         1.0f);
    int e = (__float_as_int(z) + (127 - 0x4B400000)) << 23;   // 2^n bits
    return p * __int_as_float(e);
}

// ---------------------------------------------------------------------------
// Layouts (fp16 m16n8k16 fragments, K-tile = 16):
// A: [M/16][K/16][128 u32], inner = (m&15)*8 + ((k>>1)&3)*2 + ((k>>3)&1), half=k&1
// B: [N/8 ][K/16][ 64 u32], inner = ((n&7)*4 + ((k>>1)&3))*2 + ((k>>3)&1), half=k&1
// ---------------------------------------------------------------------------

// ---------------------------------------------------------------------------
// Prep kernels: one thread per output u32 (fully coalesced writes).
// ---------------------------------------------------------------------------
__global__ __launch_bounds__(256) void prep_q(const float* __restrict__ Q) {
    const size_t o = (size_t)blockIdx.x * 256 + threadIdx.x;     // NN/16*64*128 total
    const int tile = (int)(o >> 7), w = (int)(o & 127);
    const int mt = tile >> 6, kt = tile & 63;
    const int m = mt * 16 + (w >> 3);
    const int k = kt * 16 + (w & 1) * 8 + ((w >> 1) & 3) * 2;
    const float* src = Q + (size_t)m * DD + k;
    g_Ap[o] = pack_h2(src[0] * 0.03125f, src[1] * 0.03125f);
}
__global__ __launch_bounds__(256) void prep_k(const float* __restrict__ K) {
    const size_t o = (size_t)blockIdx.x * 256 + threadIdx.x;     // NN/8*64*64 total
    const int tile = (int)(o >> 6), w = (int)(o & 63);
    const int nt = tile >> 6, kt = tile & 63;
    const int t = w >> 1, reg = w & 1;
    const int n = nt * 8 + (t >> 2);
    const int k = kt * 16 + reg * 8 + (t & 3) * 2;
    const float* src = K + (size_t)n * DD + k;
    g_Bk[o] = pack_h2(src[0], src[1]);
}
__global__ __launch_bounds__(256) void prep_v(const float* __restrict__ V) {
    const size_t o = (size_t)blockIdx.x * 256 + threadIdx.x;     // DD/8*512*64 total
    const int tile = (int)(o >> 6), w = (int)(o & 63);
    const int nt = tile >> 9, kt = tile & 511;
    const int t = w >> 1, reg = w & 1;
    const int d = nt * 8 + (t >> 2);
    const int s = kt * 16 + reg * 8 + (t & 3) * 2;
    g_Bv[o] = pack_h2(V[(size_t)s * DD + d], V[(size_t)(s + 1) * DD + d]);
}

// ---------------------------------------------------------------------------
// Unified NT fp16 GEMM: D[m,n] = sum_k A[m,k]*B[n,k]
// CTA 128x128, BK=16, 8 warps (2M x 4N), 4-stage cp.async, 1 sync/tile.
// mode 0: C = acc (fp32, ldc)    mode 1: C = acc * rowinv[m]
// ---------------------------------------------------------------------------
struct GemmParams {
    const uint32_t* Ap;
    const uint32_t* Bp;
    float* C;
    const float* rowinv;
    int ldc;
    int KT;      // K / 16
    int mode;
};

#define STAGES 4

__global__ __launch_bounds__(256, 2) void gemm_fp16(const GemmParams p) {
    __shared__ uint32_t smem[STAGES][2048];   // per stage: A 1024 u32 | B 1024 u32

    const int tid = threadIdx.x;
    const int wid = tid >> 5, lane = tid & 31;
    const int wm = wid & 1, wn = wid >> 1;
    const int bmt = blockIdx.y * 8;           // m/16 subtile base
    const int bnt = blockIdx.x * 16;          // n/8 subtile base
    const int KT = p.KT;

    // per-thread global source cursors (advance by 128 / 64 u32 per kt)
    const uint32_t* Ag = p.Ap + ((size_t)(bmt + (tid >> 5)) * KT) * 128 + (tid & 31) * 4;
    const uint32_t* Bg = p.Bp + ((size_t)(bnt + (tid >> 4)) * KT) * 64 + (tid & 15) * 4;
    const uint32_t sA = smem_u32(smem) + tid * 16;           // A chunk dst (bytes)
    const uint32_t sB = smem_u32(smem) + 4096 + tid * 16;    // B chunk dst

    float acc[4][4][4];
#pragma unroll
    for (int i = 0; i < 4; i++)
#pragma unroll
        for (int j = 0; j < 4; j++)
#pragma unroll
            for (int r = 0; r < 4; r++) acc[i][j][r] = 0.0f;

    // prologue: stages 0..2
#pragma unroll
    for (int s = 0; s < STAGES - 1; s++) {
        cp_async16(sA + s * 8192, Ag + (size_t)s * 128);
        cp_async16(sB + s * 8192, Bg + (size_t)s * 64);
        asm volatile("cp.async.commit_group;" ::: "memory");
    }

    for (int kt = 0; kt < KT; kt++) {
        asm volatile("cp.async.wait_group 2;" ::: "memory");
        __syncthreads();

        const int nk = kt + STAGES - 1;
        if (nk < KT) {
            const int s = nk & (STAGES - 1);
            cp_async16(sA + s * 8192, Ag + (size_t)nk * 128);
            cp_async16(sB + s * 8192, Bg + (size_t)nk * 64);
        }
        asm volatile("cp.async.commit_group;" ::: "memory");

        const uint32_t* bufA = &smem[kt & (STAGES - 1)][0];
        const uint32_t* bufB = &smem[kt & (STAGES - 1)][1024];

        uint2 bF[4];
#pragma unroll
        for (int nt = 0; nt < 4; nt++)
            bF[nt] = *(const uint2*)(bufB + (wn * 4 + nt) * 64 + lane * 2);

#pragma unroll
        for (int mt = 0; mt < 4; mt++) {
            const uint32_t* ab = bufA + (wm * 4 + mt) * 128 + (lane >> 2) * 8 + (lane & 3) * 2;
            const uint2 lo = *(const uint2*)ab;         // rows r:   {a0, a2}
            const uint2 hi = *(const uint2*)(ab + 64);  // rows r+8: {a1, a3}
            uint32_t a[4] = {lo.x, hi.x, lo.y, hi.y};
#pragma unroll
            for (int nt = 0; nt < 4; nt++) {
                uint32_t b[2] = {bF[nt].x, bF[nt].y};
                mma_f16(acc[mt][nt], a, b);
            }
        }
    }

    // epilogue
    const int bm = blockIdx.y * 128, bn = blockIdx.x * 128;
#pragma unroll
    for (int mt = 0; mt < 4; mt++) {
        const int row = bm + wm * 64 + mt * 16 + (lane >> 2);
        const float f0 = p.mode ? p.rowinv[row]     : 1.0f;
        const float f1 = p.mode ? p.rowinv[row + 8] : 1.0f;
#pragma unroll
        for (int nt = 0; nt < 4; nt++) {
            const int col = bn + wn * 32 + nt * 8 + (lane & 3) * 2;
            float2 o0 = make_float2(acc[mt][nt][0] * f0, acc[mt][nt][1] * f0);
            float2 o1 = make_float2(acc[mt][nt][2] * f1, acc[mt][nt][3] * f1);
            *(float2*)(p.C + (size_t)row * p.ldc + col)       = o0;
            *(float2*)(p.C + (size_t)(row + 8) * p.ldc + col) = o1;
        }
    }
}

// ---------------------------------------------------------------------------
// Softmax: read fp32 scores (linear), write exp(x-max) as fp16 into the
// A-permuted buffer g_Sp; store 1/rowsum. Exp via FMA poly (no MUFU).
// ---------------------------------------------------------------------------
__global__ __launch_bounds__(256) void softmax_kernel() {
    const int row = blockIdx.x;
    const int tid = threadIdx.x;
    const float4* src = (const float4*)(g_S + (size_t)row * NN);
    __shared__ float red[256];

    float m = -1e30f;
#pragma unroll
    for (int i = 0; i < 8; i++) {
        float4 v = src[tid + i * 256];
        m = fmaxf(m, fmaxf(fmaxf(v.x, v.y), fmaxf(v.z, v.w)));
    }
    red[tid] = m;
    __syncthreads();
#pragma unroll
    for (int s = 128; s > 0; s >>= 1) {
        if (tid < s) red[tid] = fmaxf(red[tid], red[tid + s]);
        __syncthreads();
    }
    m = red[0];
    __syncthreads();

    const size_t tile_row = (size_t)(row >> 4) * (NN / 16);
    const int inner_m = (row & 15) * 8;

    float sum = 0.0f;
#pragma unroll
    for (int i = 0; i < 8; i++) {
        const int k0 = (tid + i * 256) * 4;
        float4 v = src[tid + i * 256];
        float e0 = fexp(v.x - m), e1 = fexp(v.y - m);
        float e2 = fexp(v.z - m), e3 = fexp(v.w - m);
        sum += (e0 + e1) + (e2 + e3);
        const size_t tb = (tile_row + (k0 >> 4)) * 128 + inner_m
                        + ((k0 >> 3) & 1);             // khigh
        const int j2 = ((k0 >> 1) & 3) * 2;            // j*2 (j in {0,2})
        g_Sp[tb + j2]     = pack_h2(e0, e1);
        g_Sp[tb + j2 + 2] = pack_h2(e2, e3);
    }
    red[tid] = sum;
    __syncthreads();
#pragma unroll
    for (int s = 128; s > 0; s >>= 1) {
        if (tid < s) red[tid] = red[tid] + red[tid + s];
        __syncthreads();
    }
    if (tid == 0) g_rowinv[row] = 1.0f / red[0];
}

// ---------------------------------------------------------------------------
// Host
// ---------------------------------------------------------------------------
extern "C" void kernel_launch(void* const* d_in, const int* in_sizes, int n_in,
                              void* d_out, int out_size) {
    const float* q = (const float*)d_in[0];
    const float* k = (const float*)d_in[1];
    const float* v = (const float*)d_in[2];
    float* out = (float*)d_out;

    void *pS = nullptr, *pSp = nullptr, *pAp = nullptr, *pBk = nullptr,
         *pBv = nullptr, *pRi = nullptr;
    cudaGetSymbolAddress(&pS,  g_S);
    cudaGetSymbolAddress(&pSp, g_Sp);
    cudaGetSymbolAddress(&pAp, g_Ap);
    cudaGetSymbolAddress(&pBk, g_Bk);
    cudaGetSymbolAddress(&pBv, g_Bv);
    cudaGetSymbolAddress(&pRi, g_rowinv);

    const int half_words = (int)(((size_t)NN * DD) / 2);
    prep_q<<<half_words / 256, 256>>>(q);
    prep_k<<<half_words / 256, 256>>>(k);
    prep_v<<<half_words / 256, 256>>>(v);

    GemmParams g1;
    g1.Ap = (const uint32_t*)pAp; g1.Bp = (const uint32_t*)pBk;
    g1.C = (float*)pS; g1.rowinv = nullptr;
    g1.ldc = NN; g1.KT = DD / 16; g1.mode = 0;
    gemm_fp16<<<dim3(NN / 128, NN / 128), 256>>>(g1);

    softmax_kernel<<<NN, 256>>>();

    GemmParams g2;
    g2.Ap = (const uint32_t*)pSp; g2.Bp = (const uint32_t*)pBv;
    g2.C = out; g2.rowinv = (const float*)pRi;
    g2.ldc = DD; g2.KT = NN / 16; g2.mode = 1;
    gemm_fp16<<<dim3(DD / 128, NN / 128), 256>>>(g2);
}